// round 15
// baseline (speedup 1.0000x reference)
#include <cuda_runtime.h>
#include <cstdint>
#include <cstddef>

#define Bb 32
#define Nn 1024
#define DIM 512
#define Hh 8
#define DHd 64
#define SCALE 0.125f

// Scratch (device globals: allocation-free per harness rules)
__device__ float g_Q[Bb*Hh*Nn*DHd];   // [b,h,n,d]  tf32-rounded, pre-scaled
__device__ float g_K[Bb*Hh*Nn*DHd];   // tf32-rounded
__device__ float g_V[Bb*Hh*Nn*DHd];   // tf32-rounded
__device__ float g_O[Bb*Nn*Hh*DHd];   // [b,n,h*64+d]  tf32-rounded (attn epilogue)
__device__ float g_Xr[Bb*Nn*DIM];     // tf32-rounded x
__device__ float g_Wqt[3*Hh*DHd*DIM]; // W_qkv^T, n-major, k-chunk permuted+swizzled
__device__ float g_Wot[DIM*DIM];      // W_out^T, same layout

__device__ __forceinline__ float tf32r(float x){
    unsigned r; asm("cvt.rna.tf32.f32 %0, %1;" : "=r"(r) : "f"(x));
    return __uint_as_float(r);
}
__device__ __forceinline__ unsigned fu(float x){ return __float_as_uint(x); }
__device__ __forceinline__ uint32_t smem_u32(const void* p){
    uint32_t a;
    asm("{ .reg .u64 t; cvta.to.shared.u64 t, %1; cvt.u32.u64 %0, t; }"
        : "=r"(a) : "l"(p));
    return a;
}
__device__ __forceinline__ float f4c(const float4& v, int i){
    return i==0 ? v.x : (i==1 ? v.y : (i==2 ? v.z : v.w));
}
#define CP_ASYNC16(dst, src) \
    asm volatile("cp.async.cg.shared.global [%0], [%1], 16;" \
                 :: "r"(dst), "l"(src) : "memory")
#define CP_COMMIT() asm volatile("cp.async.commit_group;" ::: "memory")
#define CP_WAIT0()  asm volatile("cp.async.wait_group 0;" ::: "memory")

// D += A(16x8,row) * B(8x8,col)  tf32
__device__ __forceinline__ void mma8(float* d, const unsigned* a, const unsigned* b){
    asm volatile(
        "mma.sync.aligned.m16n8k8.row.col.f32.tf32.tf32.f32 "
        "{%0,%1,%2,%3},{%4,%5,%6,%7},{%8,%9},{%0,%1,%2,%3};\n"
        : "+f"(d[0]), "+f"(d[1]), "+f"(d[2]), "+f"(d[3])
        : "r"(a[0]), "r"(a[1]), "r"(a[2]), "r"(a[3]), "r"(b[0]), "r"(b[1]));
}

// ============================================================================
// Prep 0: g_Xr = tf32r(x)   (plain rounded copy)
// ============================================================================
__global__ void round_x(const float* __restrict__ x)
{
    int i = blockIdx.x * 256 + threadIdx.x;
    float4 v = ((const float4*)x)[i];
    v.x = tf32r(v.x); v.y = tf32r(v.y); v.z = tf32r(v.z); v.w = tf32r(v.w);
    ((float4*)g_Xr)[i] = v;
}

// ============================================================================
// Prep 1: W[k][n] -> Wt[n][ permuted k ], tf32-rounded.
// Within each 32-k tile: col c -> chunk (c&7)^((n&1)<<2), position c>>3.
// (chunk h holds k = {8j+h}; XOR swizzle by n-parity for conflict-free LDS.128)
// ============================================================================
__global__ void prep_w(const float* __restrict__ W, int mode)
{
    float* dst = mode ? g_Wot : g_Wqt;
    const int C = mode ? 512 : 1536;
    __shared__ float t[32][33];
    const int bx = blockIdx.x * 32, by = blockIdx.y * 32;
    const int tx = threadIdx.x, ty = threadIdx.y;
    #pragma unroll
    for (int i = 0; i < 32; i += 8)
        t[ty + i][tx] = W[(size_t)(by + ty + i) * C + bx + tx];
    __syncthreads();
    #pragma unroll
    for (int i = 0; i < 32; i += 8){
        int n  = bx + ty + i;                 // k = by + tx, c = tx
        int ch = (tx & 7) ^ ((n & 1) << 2);
        int pos = tx >> 3;
        dst[(size_t)n * 512 + by + ch * 4 + pos] = tf32r(t[tx][ty + i]);
    }
}

// ============================================================================
// GEMM v3: block 256m x 128n, 8 warps (4m x 2n), warp tile 64x64.
// Pure cp.async double-buffer (inputs pre-rounded); B frags via 2xLDS.128/nt.
// MODE 0: C = g_Xr @ g_Wqt^T -> g_Q/g_K/g_V (tf32r, Q pre-scaled).
// MODE 1: C = g_O @ g_Wot^T + bias -> out.
// SMEM: A 2x(256 rows x 144B), B 2x(128 rows x 128B) = 106,496 B.
// ============================================================================
#define GEMM_SMEM (2*256*144 + 2*128*128)

template<int MODE>
__global__ __launch_bounds__(256, 1) void gemm256(
    const float* __restrict__ bias, float* __restrict__ outp)
{
    extern __shared__ float smem[];
    const uint32_t sb = smem_u32(smem);
    const int tid = threadIdx.x, lane = tid & 31, w = tid >> 5;
    const int gr = lane >> 2, gc = lane & 3;
    const int wm = w >> 1, wn = w & 1;
    const int mBase = blockIdx.y * 256, nBase = blockIdx.x * 128;

    const float* A  = (MODE == 0) ? g_Xr : g_O;
    const float* Bt = (MODE == 0) ? g_Wqt : g_Wot;

    float* Asf[2] = { smem, smem + 256*36 };
    float* Bsf[2] = { smem + 2*256*36, smem + 2*256*36 + 128*32 };
    const uint32_t aob[2] = { 0u, 256u*144u };
    const uint32_t bob[2] = { 2u*256u*144u, 2u*256u*144u + 128u*128u };

    float acc[4][8][4];
    #pragma unroll
    for (int i=0;i<4;i++)
        #pragma unroll
        for (int j=0;j<8;j++)
            #pragma unroll
            for (int c=0;c<4;c++) acc[i][j][c] = 0.f;

    const int arow = tid >> 3, ach = tid & 7;   // idx = tid + i*256 -> row = arow+i*32

    // prologue: tile 0 -> buf 0
    {
        const float* Ag = A + (size_t)(mBase + arow)*512 + ach*4;
        #pragma unroll
        for (int i = 0; i < 8; i++)
            CP_ASYNC16(sb + aob[0] + (uint32_t)((arow + i*32)*144 + ach*16),
                       Ag + (size_t)(i*32)*512);
        const float* Bg = Bt + (size_t)(nBase + arow)*512 + ach*4;
        #pragma unroll
        for (int i = 0; i < 4; i++)
            CP_ASYNC16(sb + bob[0] + (uint32_t)((arow + i*32)*128 + ach*16),
                       Bg + (size_t)(i*32)*512);
        CP_COMMIT();
    }

    for (int kt = 0; kt < 16; kt++){
        CP_WAIT0();
        __syncthreads();

        if (kt < 15){
            const int nb = (kt + 1) & 1;
            const float* Ag = A + (size_t)(mBase + arow)*512 + (kt+1)*32 + ach*4;
            #pragma unroll
            for (int i = 0; i < 8; i++)
                CP_ASYNC16(sb + aob[nb] + (uint32_t)((arow + i*32)*144 + ach*16),
                           Ag + (size_t)(i*32)*512);
            const float* Bg = Bt + (size_t)(nBase + arow)*512 + (kt+1)*32 + ach*4;
            #pragma unroll
            for (int i = 0; i < 4; i++)
                CP_ASYNC16(sb + bob[nb] + (uint32_t)((arow + i*32)*128 + ach*16),
                           Bg + (size_t)(i*32)*512);
            CP_COMMIT();
        }

        const int buf = kt & 1;
        float* Asb = Asf[buf];
        float* Bsb = Bsf[buf];

        // B fragments for all 8 n-tiles, all 4 k-slices: 2 x LDS.128 each.
        // chunk gc (k = {8j+gc}) stored at position gc^((row&1)<<2); row parity = gr&1.
        float4 blo[8], bhi[8];
        const int plo = gc ^ ((gr & 1) << 2);
        #pragma unroll
        for (int nt = 0; nt < 8; nt++){
            const float* rp = Bsb + (wn*64 + nt*8 + gr)*32;
            blo[nt] = *(const float4*)(rp + plo*4);
            bhi[nt] = *(const float4*)(rp + (plo ^ 4)*4);
        }

        #pragma unroll
        for (int ks = 0; ks < 4; ks++){
            const int kb = ks*8;
            unsigned afr[4][4];
            #pragma unroll
            for (int mt = 0; mt < 4; mt++){
                int rr = wm*64 + mt*16;
                afr[mt][0] = fu(Asb[(rr+gr  )*36 + kb+gc  ]);
                afr[mt][1] = fu(Asb[(rr+gr+8)*36 + kb+gc  ]);
                afr[mt][2] = fu(Asb[(rr+gr  )*36 + kb+gc+4]);
                afr[mt][3] = fu(Asb[(rr+gr+8)*36 + kb+gc+4]);
            }
            #pragma unroll
            for (int nt = 0; nt < 8; nt++){
                unsigned bb[2] = { fu(f4c(blo[nt], ks)), fu(f4c(bhi[nt], ks)) };
                #pragma unroll
                for (int mt = 0; mt < 4; mt++)
                    mma8(acc[mt][nt], afr[mt], bb);
            }
        }
    }

    // epilogue
    #pragma unroll
    for (int mt=0; mt<4; mt++){
        #pragma unroll
        for (int nt=0; nt<8; nt++){
            int row = mBase + wm*64 + mt*16 + gr;
            int col = nBase + wn*64 + nt*8 + 2*gc;
            if (MODE == 0){
                int p = col >> 9, h = (col >> 6) & 7, d = col & 63;
                float* dst = (p==0 ? g_Q : (p==1 ? g_K : g_V));
                float sc = (p==0) ? SCALE : 1.0f;
                #pragma unroll
                for (int rr=0; rr<2; rr++){
                    int r = row + rr*8;
                    int b = r >> 10, n = r & 1023;
                    *(float2*)(dst + ((size_t)((b*8+h)*1024 + n))*64 + d) =
                        make_float2(tf32r(acc[mt][nt][rr*2]   * sc),
                                    tf32r(acc[mt][nt][rr*2+1] * sc));
                }
            } else {
                float b0 = bias[col], b1 = bias[col+1];
                *(float2*)(outp + (size_t)row*512 + col) =
                    make_float2(acc[mt][nt][0] + b0, acc[mt][nt][1] + b1);
                *(float2*)(outp + (size_t)(row+8)*512 + col) =
                    make_float2(acc[mt][nt][2] + b0, acc[mt][nt][3] + b1);
            }
        }
    }
}

// ============================================================================
// Attention v4 (R14 measured; only change: g_O stores tf32-rounded so the
// out-GEMM can cp.async it directly — bit-identical to prior rounding-on-load)
// ============================================================================
#define QS 68
#define VS 72
#define PS 68
#define KVBUF (64*QS + 64*VS)
#define ATT_SMEM ((128*PS + 2*KVBUF)*4)

__global__ __launch_bounds__(256, 2) void attn_kernel(const float* __restrict__ mask)
{
    extern __shared__ float sm[];
    float* Ps  = sm;
    float* KV0 = sm + 128*PS;
    float* KV1 = KV0 + KVBUF;

    const int tid = threadIdx.x, lane = tid & 31, w = tid >> 5;
    const int gr = lane >> 2, gc = lane & 3;
    const int b = blockIdx.z, h = blockIdx.y, rt = blockIdx.x;
    const int r0 = w * 16;

    const float* Qg = g_Q + ((size_t)((b*8+h)*1024 + rt*128))*64;
    const float* Kg = g_K + ((size_t)((b*8+h)*1024))*64;
    const float* Vg = g_V + ((size_t)((b*8+h)*1024))*64;
    const float* Mg = mask + ((size_t)(h*1024 + rt*128))*1024;

    const uint32_t ps_a  = smem_u32(Ps);
    const uint32_t kv_a[2] = { smem_u32(KV0), smem_u32(KV1) };

    {
        #pragma unroll
        for (int ii = 0; ii < 8; ii++){
            int idx = tid + ii*256;
            int r = idx >> 4, c = (idx & 15) << 2;
            CP_ASYNC16(ps_a + (uint32_t)(r*PS + c)*4, Qg + r*64 + c);
        }
        #pragma unroll
        for (int ii = 0; ii < 4; ii++){
            int idx = tid + ii*256;
            int r = idx >> 4, c = (idx & 15) << 2;
            CP_ASYNC16(kv_a[0] + (uint32_t)(r*QS + c)*4, Kg + r*64 + c);
            CP_ASYNC16(kv_a[0] + (uint32_t)(64*QS + r*VS + c)*4, Vg + r*64 + c);
        }
        CP_COMMIT();
    }

    unsigned q[8][4];
    float o[8][4];
    #pragma unroll
    for (int i=0;i<8;i++){ o[i][0]=0.f;o[i][1]=0.f;o[i][2]=0.f;o[i][3]=0.f; }
    float mrow0 = -1e30f, mrow1 = -1e30f, lrow0 = 0.f, lrow1 = 0.f;

    for (int jt = 0; jt < 16; jt++){
        CP_WAIT0();
        __syncthreads();

        float* Kb = (jt & 1) ? KV1 : KV0;
        float* Vb = Kb + 64*QS;

        if (jt == 0){
            #pragma unroll
            for (int ks = 0; ks < 8; ks++){
                int kb = ks*8;
                q[ks][0]=fu(Ps[(r0+gr  )*PS + kb+gc  ]);
                q[ks][1]=fu(Ps[(r0+gr+8)*PS + kb+gc  ]);
                q[ks][2]=fu(Ps[(r0+gr  )*PS + kb+gc+4]);
                q[ks][3]=fu(Ps[(r0+gr+8)*PS + kb+gc+4]);
            }
        }

        if (jt < 15){
            const float* kp = Kg + (jt+1)*64*64;
            const float* vp = Vg + (jt+1)*64*64;
            uint32_t dst = kv_a[(jt+1) & 1];
            #pragma unroll
            for (int ii = 0; ii < 4; ii++){
                int idx = tid + ii*256;
                int r = idx >> 4, c = (idx & 15) << 2;
                CP_ASYNC16(dst + (uint32_t)(r*QS + c)*4, kp + r*64 + c);
                CP_ASYNC16(dst + (uint32_t)(64*QS + r*VS + c)*4, vp + r*64 + c);
            }
            CP_COMMIT();
        }

        float s[8][4];
        #pragma unroll
        for (int i=0;i<8;i++){ s[i][0]=0.f;s[i][1]=0.f;s[i][2]=0.f;s[i][3]=0.f; }
        #pragma unroll
        for (int ks=0; ks<8; ks++){
            int kb = ks*8;
            #pragma unroll
            for (int nt=0; nt<8; nt++){
                int n0 = nt*8;
                unsigned bb[2] = {
                    fu(Kb[(n0+gr)*QS + kb+gc  ]),
                    fu(Kb[(n0+gr)*QS + kb+gc+4]) };
                mma8(s[nt], q[ks], bb);
            }
        }

        float ml0 = -1e30f, ml1 = -1e30f;
        #pragma unroll
        for (int nt=0; nt<8; nt++){
            ml0 = fmaxf(ml0, fmaxf(s[nt][0], s[nt][1]));
            ml1 = fmaxf(ml1, fmaxf(s[nt][2], s[nt][3]));
        }
        ml0 = fmaxf(ml0, __shfl_xor_sync(0xffffffffu, ml0, 1));
        ml0 = fmaxf(ml0, __shfl_xor_sync(0xffffffffu, ml0, 2));
        ml1 = fmaxf(ml1, __shfl_xor_sync(0xffffffffu, ml1, 1));
        ml1 = fmaxf(ml1, __shfl_xor_sync(0xffffffffu, ml1, 2));
        float mn0 = fmaxf(mrow0, ml0), mn1 = fmaxf(mrow1, ml1);
        float al0 = __expf(mrow0 - mn0), al1 = __expf(mrow1 - mn1);
        mrow0 = mn0; mrow1 = mn1;

        float ls0 = 0.f, ls1 = 0.f;
        const float* mrp0 = Mg + (size_t)(r0+gr  )*1024 + jt*64;
        const float* mrp1 = Mg + (size_t)(r0+gr+8)*1024 + jt*64;
        #pragma unroll
        for (int nt=0; nt<8; nt++){
            int cc = nt*8 + 2*gc;
            float e0 = __expf(s[nt][0]-mn0), e1 = __expf(s[nt][1]-mn0);
            float e2 = __expf(s[nt][2]-mn1), e3 = __expf(s[nt][3]-mn1);
            ls0 += e0 + e1; ls1 += e2 + e3;
            float2 mk0 = *(const float2*)(mrp0 + cc);
            float2 mk1 = *(const float2*)(mrp1 + cc);
            *(float2*)(Ps + (r0+gr  )*PS + cc) =
                make_float2(tf32r(e0*mk0.x), tf32r(e1*mk0.y));
            *(float2*)(Ps + (r0+gr+8)*PS + cc) =
                make_float2(tf32r(e2*mk1.x), tf32r(e3*mk1.y));
        }
        lrow0 = lrow0*al0 + ls0;
        lrow1 = lrow1*al1 + ls1;
        #pragma unroll
        for (int nt=0; nt<8; nt++){
            o[nt][0]*=al0; o[nt][1]*=al0; o[nt][2]*=al1; o[nt][3]*=al1;
        }
        __syncwarp();

        #pragma unroll
        for (int ks=0; ks<8; ks++){
            int kb = ks*8;
            unsigned a[4] = {
                fu(Ps[(r0+gr  )*PS + kb+gc  ]),
                fu(Ps[(r0+gr+8)*PS + kb+gc  ]),
                fu(Ps[(r0+gr  )*PS + kb+gc+4]),
                fu(Ps[(r0+gr+8)*PS + kb+gc+4]) };
            #pragma unroll
            for (int nt=0; nt<8; nt++){
                int n0 = nt*8;
                unsigned bb[2] = {
                    fu(Vb[(kb+gc  )*VS + n0+gr]),
                    fu(Vb[(kb+gc+4)*VS + n0+gr]) };
                mma8(o[nt], a, bb);
            }
        }
    }

    lrow0 += __shfl_xor_sync(0xffffffffu, lrow0, 1);
    lrow0 += __shfl_xor_sync(0xffffffffu, lrow0, 2);
    lrow1 += __shfl_xor_sync(0xffffffffu, lrow1, 1);
    lrow1 += __shfl_xor_sync(0xffffffffu, lrow1, 2);
    float inv0 = 1.f / lrow0, inv1 = 1.f / lrow1;

    float* Og = g_O + ((size_t)(b*1024 + rt*128))*512 + h*64;
    #pragma unroll
    for (int nt=0; nt<8; nt++){
        int d = nt*8 + 2*gc;
        *(float2*)(Og + (size_t)(r0+gr  )*512 + d) =
            make_float2(tf32r(o[nt][0]*inv0), tf32r(o[nt][1]*inv0));
        *(float2*)(Og + (size_t)(r0+gr+8)*512 + d) =
            make_float2(tf32r(o[nt][2]*inv1), tf32r(o[nt][3]*inv1));
    }
}

// ============================================================================
extern "C" void kernel_launch(void* const* d_in, const int* in_sizes, int n_in,
                              void* d_out, int out_size)
{
    (void)in_sizes; (void)n_in; (void)out_size;
    const float* x    = (const float*)d_in[0];
    const float* Wqkv = (const float*)d_in[1];
    const float* Wout = (const float*)d_in[2];
    const float* bout = (const float*)d_in[3];
    const float* mask = (const float*)d_in[4];
    float* out = (float*)d_out;

    cudaFuncSetAttribute(gemm256<0>,
                         cudaFuncAttributeMaxDynamicSharedMemorySize, GEMM_SMEM);
    cudaFuncSetAttribute(gemm256<1>,
                         cudaFuncAttributeMaxDynamicSharedMemorySize, GEMM_SMEM);
    cudaFuncSetAttribute(attn_kernel,
                         cudaFuncAttributeMaxDynamicSharedMemorySize, ATT_SMEM);

    round_x<<<16384, 256>>>(x);
    prep_w<<<dim3(48, 16), dim3(32, 8)>>>(Wqkv, 0);
    prep_w<<<dim3(16, 16), dim3(32, 8)>>>(Wout, 1);
    gemm256<0><<<dim3(12, 128), 256, GEMM_SMEM>>>(nullptr, nullptr);
    attn_kernel<<<dim3(8, 8, 32), 256, ATT_SMEM>>>(mask);
    gemm256<1><<<dim3(4, 128), 256, GEMM_SMEM>>>(bout, out);
}